// round 15
// baseline (speedup 1.0000x reference)
#include <cuda_runtime.h>
#include <cuda_fp16.h>
#include <math.h>
#include <stdint.h>

#define BATCH 8
#define LSEQ  1024
#define HID   768
#define NH    12
#define DH    64
#define MLPD  3072
#define MROWS (BATCH*LSEQ)    // 8192
#define NHEADS_TOT (BATCH*NH) // 96

// ---------------- static scratch ----------------
__device__ float  g_QK [(size_t)MROWS*2*HID];  // split-K partials
__device__ float  g_x1f[MROWS*HID];
__device__ __half g_Qhh[MROWS*HID];
__device__ __half g_Khh[MROWS*HID];
__device__ __half g_xh  [MROWS*HID];
__device__ __half g_Ctxh[MROWS*HID];
__device__ __half g_x1h [MROWS*HID];
__device__ __half g_Hfh [(size_t)MROWS*MLPD];
__device__ __half g_Wqkh[(size_t)2*HID*HID];   // [1536][768] N-major (Wq pre-scaled 1/8)
__device__ __half g_Worh[HID*HID];
__device__ __half g_W1h [(size_t)MLPD*HID];
__device__ __half g_W2h [(size_t)HID*MLPD];

// ---------------- helpers ----------------
__device__ __forceinline__ float gelu_f(float v) {
    return 0.5f * v * (1.0f + erff(v * 0.7071067811865475f));
}

__device__ __forceinline__ void mma_f16(float* d, const uint32_t* a, const uint32_t* b) {
    asm volatile(
        "mma.sync.aligned.m16n8k16.row.col.f32.f16.f16.f32 "
        "{%0,%1,%2,%3}, {%4,%5,%6,%7}, {%8,%9}, {%0,%1,%2,%3};\n"
        : "+f"(d[0]), "+f"(d[1]), "+f"(d[2]), "+f"(d[3])
        : "r"(a[0]), "r"(a[1]), "r"(a[2]), "r"(a[3]),
          "r"(b[0]), "r"(b[1]));
}

__device__ __forceinline__ void ldsm4(uint32_t* r, uint32_t addr) {
    asm volatile("ldmatrix.sync.aligned.m8n8.x4.shared.b16 {%0,%1,%2,%3}, [%4];"
        : "=r"(r[0]), "=r"(r[1]), "=r"(r[2]), "=r"(r[3]) : "r"(addr));
}

__device__ __forceinline__ void ldsm4t(uint32_t* r, uint32_t addr) {
    asm volatile("ldmatrix.sync.aligned.m8n8.x4.trans.shared.b16 {%0,%1,%2,%3}, [%4];"
        : "=r"(r[0]), "=r"(r[1]), "=r"(r[2]), "=r"(r[3]) : "r"(addr));
}

__device__ __forceinline__ void cp16(uint32_t dst, const void* src) {
    asm volatile("cp.async.cg.shared.global [%0], [%1], 16;\n" :: "r"(dst), "l"(src));
}
__device__ __forceinline__ void cp_commit() {
    asm volatile("cp.async.commit_group;\n");
}
template<int N>
__device__ __forceinline__ void cp_wait() {
    asm volatile("cp.async.wait_group %0;\n" :: "n"(N));
}

enum { EPI_NONE = 0, EPI_BIAS_GELU = 2 };
enum { OUT_F32 = 0, OUT_F16 = 1, OUT_HEADS = 2 };

// ---------------- FP16 tensor-core GEMM: C = A(MxK) @ Bt(NxK)^T ----------------
#define HS_STR 40
#define STAGES 4
#define TILE_HALVES (128 * HS_STR)
#define TILE_BYTES  (TILE_HALVES * 2)
#define GEMM_SMEM_BYTES (STAGES * 2 * TILE_BYTES)

#define GEMM_CORE_LOOP(aBase, bBase) \
    _Pragma("unroll") \
    for (int kk = 0; kk < 32; kk += 16) { \
        uint32_t a[4][4], b[4][2]; \
        _Pragma("unroll") \
        for (int mt = 0; mt < 4; mt++) \
            ldsm4(a[mt], (aBase) + (uint32_t)((wm + mt * 16 + rl16) * HS_STR + kk + ko8) * 2); \
        _Pragma("unroll") \
        for (int nb = 0; nb < 2; nb++) { \
            uint32_t t4[4]; \
            ldsm4(t4, (bBase) + (uint32_t)((wn + nb * 16 + brow) * HS_STR + kk + bko) * 2); \
            b[2 * nb][0]     = t4[0]; \
            b[2 * nb][1]     = t4[1]; \
            b[2 * nb + 1][0] = t4[2]; \
            b[2 * nb + 1][1] = t4[3]; \
        } \
        _Pragma("unroll") \
        for (int mt = 0; mt < 4; mt++) \
            _Pragma("unroll") \
            for (int nt = 0; nt < 4; nt++) \
                mma_f16(acc[mt][nt], a[mt], b[nt]); \
    }

template<int EPI, int OUT>
__global__ __launch_bounds__(256, 2) void gemm_h(
    const __half* __restrict__ A, const __half* __restrict__ Bt,
    void* __restrict__ Cv, void* __restrict__ Cv2,
    const float* __restrict__ bias, int M, int N, int K)
{
    extern __shared__ __half hsm[];
    const uint32_t sA = (uint32_t)__cvta_generic_to_shared(hsm);
    const uint32_t sB = sA + STAGES * TILE_BYTES;

    const int tid  = threadIdx.x;
    const int lane = tid & 31;
    const int warp = tid >> 5;
    const int grp  = lane >> 2;
    const int tg   = lane & 3;
    const int wm   = (warp >> 2) * 64;
    const int wn   = (warp & 3) * 32;
    const int bx   = blockIdx.x;
    const int by   = blockIdx.y;

    const int rl16 = lane & 15;
    const int ko8  = (lane >> 4) << 3;
    const int brow = (lane & 7) + ((lane >> 4) << 3);
    const int bko  = ((lane >> 3) & 1) << 3;

    const __half* Abase = A  + (size_t)(by * 128) * K;
    const __half* Bbase = Bt + (size_t)(bx * 128) * K;

    float acc[4][4][4];
    #pragma unroll
    for (int i = 0; i < 4; i++)
        #pragma unroll
        for (int j = 0; j < 4; j++)
            #pragma unroll
            for (int r = 0; r < 4; r++) acc[i][j][r] = 0.0f;

    const int nt_ = K >> 5;

    auto issue = [&](int t) {
        const int st = t & (STAGES - 1);
        const int k0 = t << 5;
        const uint32_t aoff = sA + st * TILE_BYTES;
        const uint32_t boff = sB + st * TILE_BYTES;
        #pragma unroll
        for (int i = 0; i < 2; i++) {
            const int c = tid + 256 * i;
            const int r = c >> 2, ch = (c & 3) * 8;
            cp16(aoff + (uint32_t)(r * HS_STR + ch) * 2, Abase + (size_t)r * K + k0 + ch);
            cp16(boff + (uint32_t)(r * HS_STR + ch) * 2, Bbase + (size_t)r * K + k0 + ch);
        }
        cp_commit();
    };

    #pragma unroll
    for (int t = 0; t < STAGES - 1; t++) issue(t);

    for (int t = 0; t < nt_; t++) {
        cp_wait<STAGES - 2>();
        __syncthreads();
        const int cur = t & (STAGES - 1);
        const uint32_t aBase = sA + cur * TILE_BYTES;
        const uint32_t bBase = sB + cur * TILE_BYTES;
        GEMM_CORE_LOOP(aBase, bBase)
        if (t + STAGES - 1 < nt_) issue(t + STAGES - 1);
        else cp_commit();
    }

    #pragma unroll
    for (int mt = 0; mt < 4; mt++) {
        #pragma unroll
        for (int nt = 0; nt < 4; nt++) {
            const int r0 = by * 128 + wm + mt * 16 + grp;
            const int c0 = bx * 128 + wn + nt * 8 + tg * 2;
            float v0 = acc[mt][nt][0], v1 = acc[mt][nt][1];
            float v2 = acc[mt][nt][2], v3 = acc[mt][nt][3];
            if (EPI == EPI_BIAS_GELU) {
                const float2 bv = *(const float2*)&bias[c0];
                v0 = gelu_f(v0 + bv.x); v1 = gelu_f(v1 + bv.y);
                v2 = gelu_f(v2 + bv.x); v3 = gelu_f(v3 + bv.y);
            }
            if (OUT == OUT_F16) {
                __half* Ch = (__half*)Cv;
                *(__half2*)&Ch[(size_t)r0 * N + c0] = __floats2half2_rn(v0, v1);
                *(__half2*)&Ch[(size_t)(r0 + 8) * N + c0] = __floats2half2_rn(v2, v3);
            } else if (OUT == OUT_F32) {
                float* Cf = (float*)Cv;
                float2 w0 = {v0, v1}, w1 = {v2, v3};
                *(float2*)&Cf[(size_t)r0 * N + c0] = w0;
                *(float2*)&Cf[(size_t)(r0 + 8) * N + c0] = w1;
            } else {
                // OUT_HEADS: scatter directly into head-major Qh / Kh
                __half* Qd = (__half*)Cv;
                __half* Kd = (__half*)Cv2;
                const int b_ = r0 >> 10;
                const int l  = r0 & 1023;
                const float vv[2][2] = {{v0, v1}, {v2, v3}};
                #pragma unroll
                for (int rr = 0; rr < 2; rr++) {
                    const int ll = l + rr * 8;
                    #pragma unroll
                    for (int cc = 0; cc < 2; cc++) {
                        const int c = c0 + cc;
                        const bool isQ = (c < HID);
                        const int h = isQ ? c : (c - HID);   // FIX: 768 not pow2
                        const int d = h / NH, n2 = h % NH;
                        __half* T = isQ ? Qd : Kd;
                        T[(((size_t)(b_ * NH + n2) << 10) + ll) * DH + d] =
                            __float2half_rn(vv[rr][cc]);
                    }
                }
            }
        }
    }
}

// ---------------- FP16 split-K=2 partial GEMM ----------------
__global__ __launch_bounds__(256, 2) void gemm_h_splitk(
    const __half* __restrict__ A, const __half* __restrict__ Bt, float* __restrict__ Cp,
    int M, int N, int ldk, int Khalf)
{
    extern __shared__ __half hsm[];
    const uint32_t sA = (uint32_t)__cvta_generic_to_shared(hsm);
    const uint32_t sB = sA + STAGES * TILE_BYTES;

    const int tid  = threadIdx.x;
    const int lane = tid & 31;
    const int warp = tid >> 5;
    const int grp  = lane >> 2;
    const int tg   = lane & 3;
    const int wm   = (warp >> 2) * 64;
    const int wn   = (warp & 3) * 32;
    const int bx   = blockIdx.x;
    const int by   = blockIdx.y;
    const int z    = blockIdx.z;

    const int rl16 = lane & 15;
    const int ko8  = (lane >> 4) << 3;
    const int brow = (lane & 7) + ((lane >> 4) << 3);
    const int bko  = ((lane >> 3) & 1) << 3;

    const __half* Abase = A  + (size_t)(by * 128) * ldk + (size_t)z * Khalf;
    const __half* Bbase = Bt + (size_t)(bx * 128) * ldk + (size_t)z * Khalf;

    float acc[4][4][4];
    #pragma unroll
    for (int i = 0; i < 4; i++)
        #pragma unroll
        for (int j = 0; j < 4; j++)
            #pragma unroll
            for (int r = 0; r < 4; r++) acc[i][j][r] = 0.0f;

    const int nt_ = Khalf >> 5;

    auto issue = [&](int t) {
        const int st = t & (STAGES - 1);
        const int k0 = t << 5;
        const uint32_t aoff = sA + st * TILE_BYTES;
        const uint32_t boff = sB + st * TILE_BYTES;
        #pragma unroll
        for (int i = 0; i < 2; i++) {
            const int c = tid + 256 * i;
            const int r = c >> 2, ch = (c & 3) * 8;
            cp16(aoff + (uint32_t)(r * HS_STR + ch) * 2, Abase + (size_t)r * ldk + k0 + ch);
            cp16(boff + (uint32_t)(r * HS_STR + ch) * 2, Bbase + (size_t)r * ldk + k0 + ch);
        }
        cp_commit();
    };

    #pragma unroll
    for (int t = 0; t < STAGES - 1; t++) issue(t);

    for (int t = 0; t < nt_; t++) {
        cp_wait<STAGES - 2>();
        __syncthreads();
        const int cur = t & (STAGES - 1);
        const uint32_t aBase = sA + cur * TILE_BYTES;
        const uint32_t bBase = sB + cur * TILE_BYTES;
        GEMM_CORE_LOOP(aBase, bBase)
        if (t + STAGES - 1 < nt_) issue(t + STAGES - 1);
        else cp_commit();
    }

    float* Cz = Cp + (size_t)z * M * N;
    #pragma unroll
    for (int mt = 0; mt < 4; mt++) {
        #pragma unroll
        for (int nt = 0; nt < 4; nt++) {
            const int r0 = by * 128 + wm + mt * 16 + grp;
            const int c0 = bx * 128 + wn + nt * 8 + tg * 2;
            float2 w0 = {acc[mt][nt][0], acc[mt][nt][1]};
            float2 w1 = {acc[mt][nt][2], acc[mt][nt][3]};
            *(float2*)&Cz[(size_t)r0 * N + c0] = w0;
            *(float2*)&Cz[(size_t)(r0 + 8) * N + c0] = w1;
        }
    }
}

// ---------------- fused split-K reduce + layernorm ----------------
template<bool BIAS, bool HOUT>
__global__ __launch_bounds__(256) void layernorm_fused_k(
    const float* __restrict__ p, const float* __restrict__ bias,
    const float* __restrict__ res, const float* __restrict__ g,
    const float* __restrict__ be, float* __restrict__ Yf, __half* __restrict__ Yh)
{
    const int row = blockIdx.x;
    const float* p0 = p + (size_t)row * HID;
    const float* p1 = p + (size_t)MROWS * HID + (size_t)row * HID;
    const float* r  = res + (size_t)row * HID;
    const int tid = threadIdx.x;
    __shared__ float vbuf[HID];
    __shared__ float shs[8], shss[8];

    float s = 0.0f, ss = 0.0f;
    for (int c = tid; c < HID; c += 256) {
        float v = p0[c] + p1[c] + r[c];
        if (BIAS) v += bias[c];
        vbuf[c] = v;
        s += v;
        ss = fmaf(v, v, ss);
    }
    #pragma unroll
    for (int o = 16; o; o >>= 1) {
        s  += __shfl_xor_sync(0xffffffffu, s, o);
        ss += __shfl_xor_sync(0xffffffffu, ss, o);
    }
    if ((tid & 31) == 0) { shs[tid >> 5] = s; shss[tid >> 5] = ss; }
    __syncthreads();
    if (tid == 0) {
        float a = 0.0f, b = 0.0f;
        #pragma unroll
        for (int i = 0; i < 8; i++) { a += shs[i]; b += shss[i]; }
        shs[0] = a; shss[0] = b;
    }
    __syncthreads();
    const float mu  = shs[0]  * (1.0f / HID);
    const float var = shss[0] * (1.0f / HID) - mu * mu;
    const float inv = rsqrtf(var + 1e-5f);
    for (int c = tid; c < HID; c += 256) {
        float v = (vbuf[c] - mu) * inv * g[c] + be[c];
        Yf[(size_t)row * HID + c] = v;
        if (HOUT) Yh[(size_t)row * HID + c] = __float2half_rn(v);
    }
}

// ---------------- merged weight transpose+fp16 (one launch) ----------------
#define TQ  576
#define T1  2304
#define TALL (3*TQ + 2*T1)

__global__ void transpose_all_k(const float* __restrict__ Wq, const float* __restrict__ Wk,
                                const float* __restrict__ Wo, const float* __restrict__ W1,
                                const float* __restrict__ W2) {
    __shared__ float tb[32][33];
    int bid = blockIdx.x;
    const float* W; __half* Wt; int K, N, nx; float scale = 1.0f;
    if (bid < TQ)            { W = Wq; Wt = g_Wqkh;                       K = HID;  N = HID;  nx = 24; scale = 0.125f; }
    else if (bid < 2 * TQ)   { bid -= TQ;     W = Wk; Wt = g_Wqkh + (size_t)HID * HID; K = HID;  N = HID;  nx = 24; }
    else if (bid < 3 * TQ)   { bid -= 2 * TQ; W = Wo; Wt = g_Worh;        K = HID;  N = HID;  nx = 24; }
    else if (bid < 3 * TQ + T1) { bid -= 3 * TQ; W = W1; Wt = g_W1h;      K = HID;  N = MLPD; nx = 96; }
    else                     { bid -= 3 * TQ + T1; W = W2; Wt = g_W2h;    K = MLPD; N = HID;  nx = 24; }
    const int n0 = (bid % nx) * 32;
    const int k0 = (bid / nx) * 32;
    const int tx = threadIdx.x, ty = threadIdx.y;
    #pragma unroll
    for (int j = ty; j < 32; j += 8)
        tb[j][tx] = W[(size_t)(k0 + j) * N + n0 + tx];
    __syncthreads();
    #pragma unroll
    for (int j = ty; j < 32; j += 8)
        Wt[(size_t)(n0 + j) * K + k0 + tx] = __float2half_rn(tb[tx][j] * scale);
}

__global__ void tohalf_k(const float4* __restrict__ in, __half2* __restrict__ out, int n4) {
    int i = blockIdx.x * blockDim.x + threadIdx.x;
    if (i >= n4) return;
    float4 v = in[i];
    out[2 * i]     = __floats2half2_rn(v.x, v.y);
    out[2 * i + 1] = __floats2half2_rn(v.z, v.w);
}

// ---------------- FP16 fused flash attention (ldsm.trans for O-mma B) ----------------
#define AQ_STR  72    // halves per Q/K row (64 + 8 pad)
#define APS_STR 136   // halves per Ps row (128 + 8 pad)
#define ATTN_HALVES (128*AQ_STR + 128*AQ_STR + 128*APS_STR)
#define ATTN_FLOATS (128 + 128 + 512 + 512)
#define ATTN_SMEM_BYTES (ATTN_HALVES * 2 + ATTN_FLOATS * 4)

__global__ __launch_bounds__(256) void attn_fused(
    const __half* __restrict__ Qh, const __half* __restrict__ Kh, __half* __restrict__ Ctx)
{
    extern __shared__ __half asm_[];
    __half* Qs = asm_;                     // [128][AQ_STR]
    __half* Ks = Qs + 128 * AQ_STR;        // [128][AQ_STR]  (key-major)
    __half* Ps = Ks + 128 * AQ_STR;        // [128][APS_STR]
    float* Mrow = (float*)(Ps + 128 * APS_STR);
    float* Srow = Mrow + 128;
    float* red1 = Srow + 128;
    float* red2 = red1 + 512;

    const uint32_t qA = (uint32_t)__cvta_generic_to_shared(Qs);
    const uint32_t kA = (uint32_t)__cvta_generic_to_shared(Ks);
    const uint32_t pA = (uint32_t)__cvta_generic_to_shared(Ps);

    const int z   = blockIdx.y;
    const int l0  = blockIdx.x * 128;
    const int tid = threadIdx.x;
    const int lane = tid & 31;
    const int warp = tid >> 5;
    const int grp  = lane >> 2;
    const int tg   = lane & 3;
    const int wm   = (warp >> 2) * 64;
    const int wn   = (warp & 3) * 32;
    const int wn2  = (warp & 3) * 16;
    const int wc   = warp & 3;

    const int rl16 = lane & 15;
    const int ko8  = (lane >> 4) << 3;
    const int brow = (lane & 7) + ((lane >> 4) << 3);
    const int bko  = ((lane >> 3) & 1) << 3;
    const int la15 = lane & 15;
    const int lg8  = (lane >> 4) << 3;

    const __half* Qbase = Qh + ((size_t)z * LSEQ + l0) * DH;
    const __half* Kbase = Kh + (size_t)z * LSEQ * DH;

    if (tid < 128) { Mrow[tid] = -3.0e38f; Srow[tid] = 0.0f; }

    #pragma unroll
    for (int i = 0; i < 8; i++) {
        const int f = tid + 256 * i;
        const int r = f >> 4, c4 = (f & 15) * 4;
        uint2 v = *(const uint2*)(Qbase + r * DH + c4);
        *(uint2*)&Qs[r * AQ_STR + c4] = v;
    }

    float acc_o[4][2][4];
    #pragma unroll
    for (int i = 0; i < 4; i++)
        #pragma unroll
        for (int j = 0; j < 2; j++)
            #pragma unroll
            for (int r = 0; r < 4; r++) acc_o[i][j][r] = 0.0f;

    __syncthreads();

    for (int mtile = 0; mtile < LSEQ / 128; mtile++) {
        const __half* Kt = Kbase + (size_t)mtile * 128 * DH;
        #pragma unroll
        for (int i = 0; i < 8; i++) {
            const int f = tid + 256 * i;
            const int r = f >> 4, c4 = (f & 15) * 4;
            uint2 v = *(const uint2*)(Kt + r * DH + c4);
            *(uint2*)&Ks[r * AQ_STR + c4] = v;
        }
        __syncthreads();

        // ---- S = Q @ K^T (fp16 mma, K=64) ----
        float s[4][4][4];
        #pragma unroll
        for (int i = 0; i < 4; i++)
            #pragma unroll
            for (int j = 0; j < 4; j++)
                #pragma unroll
                for (int r = 0; r < 4; r++) s[i][j][r] = 0.0f;

        #pragma unroll
        for (int kk = 0; kk < DH; kk += 16) {
            uint32_t a[4][4], b[4][2];
            #pragma unroll
            for (int mt = 0; mt < 4; mt++)
                ldsm4(a[mt], qA + (uint32_t)((wm + mt * 16 + rl16) * AQ_STR + kk + ko8) * 2);
            #pragma unroll
            for (int nb = 0; nb < 2; nb++) {
                uint32_t t4[4];
                ldsm4(t4, kA + (uint32_t)((wn + nb * 16 + brow) * AQ_STR + kk + bko) * 2);
                b[2 * nb][0]     = t4[0];
                b[2 * nb][1]     = t4[1];
                b[2 * nb + 1][0] = t4[2];
                b[2 * nb + 1][1] = t4[3];
            }
            #pragma unroll
            for (int mt = 0; mt < 4; mt++)
                #pragma unroll
                for (int nt = 0; nt < 4; nt++)
                    mma_f16(s[mt][nt], a[mt], b[nt]);
        }

        // ---- Phase A ----
        #pragma unroll
        for (int mt = 0; mt < 4; mt++) {
            float mlo = -3.0e38f, mhi = -3.0e38f;
            #pragma unroll
            for (int nt = 0; nt < 4; nt++) {
                mlo = fmaxf(mlo, fmaxf(s[mt][nt][0], s[mt][nt][1]));
                mhi = fmaxf(mhi, fmaxf(s[mt][nt][2], s[mt][nt][3]));
            }
            mlo = fmaxf(mlo, __shfl_xor_sync(0xffffffffu, mlo, 1));
            mlo = fmaxf(mlo, __shfl_xor_sync(0xffffffffu, mlo, 2));
            mhi = fmaxf(mhi, __shfl_xor_sync(0xffffffffu, mhi, 1));
            mhi = fmaxf(mhi, __shfl_xor_sync(0xffffffffu, mhi, 2));
            if (tg == 0) {
                red1[(wm + mt * 16 + grp) * 4 + wc]     = mlo;
                red1[(wm + mt * 16 + grp + 8) * 4 + wc] = mhi;
            }
        }
        __syncthreads();

        // ---- Phase B ----
        float newlo[4], newhi[4], scllo[4], sclhi[4];
        #pragma unroll
        for (int mt = 0; mt < 4; mt++) {
            const int rlo = wm + mt * 16 + grp;
            const int rhi = rlo + 8;
            float4 v1 = *(const float4*)&red1[rlo * 4];
            float4 v2 = *(const float4*)&red1[rhi * 4];
            float tlo = fmaxf(fmaxf(v1.x, v1.y), fmaxf(v1.z, v1.w));
            float thi = fmaxf(fmaxf(v2.x, v2.y), fmaxf(v2.z, v2.w));
            float oldlo = Mrow[rlo], oldhi = Mrow[rhi];
            float nlo = fmaxf(oldlo, tlo), nhi = fmaxf(oldhi, thi);
            newlo[mt] = nlo; newhi[mt] = nhi;
            scllo[mt] = __expf(oldlo - nlo);
            sclhi[mt] = __expf(oldhi - nhi);

            float pslo = 0.0f, pshi = 0.0f;
            #pragma unroll
            for (int nt = 0; nt < 4; nt++) {
                const int c = wn + nt * 8 + 2 * tg;
                float p0 = __expf(s[mt][nt][0] - nlo);
                float p1 = __expf(s[mt][nt][1] - nlo);
                float p2 = __expf(s[mt][nt][2] - nhi);
                float p3 = __expf(s[mt][nt][3] - nhi);
                *(__half2*)&Ps[rlo * APS_STR + c] = __floats2half2_rn(p0, p1);
                *(__half2*)&Ps[rhi * APS_STR + c] = __floats2half2_rn(p2, p3);
                pslo += p0 + p1;
                pshi += p2 + p3;
            }
            pslo += __shfl_xor_sync(0xffffffffu, pslo, 1);
            pslo += __shfl_xor_sync(0xffffffffu, pslo, 2);
            pshi += __shfl_xor_sync(0xffffffffu, pshi, 1);
            pshi += __shfl_xor_sync(0xffffffffu, pshi, 2);
            if (tg == 0) {
                red2[rlo * 4 + wc] = pslo;
                red2[rhi * 4 + wc] = pshi;
            }
            #pragma unroll
            for (int nt2 = 0; nt2 < 2; nt2++) {
                acc_o[mt][nt2][0] *= scllo[mt];
                acc_o[mt][nt2][1] *= scllo[mt];
                acc_o[mt][nt2][2] *= sclhi[mt];
                acc_o[mt][nt2][3] *= sclhi[mt];
            }
        }
        __syncthreads();

        // ---- Phase C ----
        if (wc == 0 && tg == 0) {
            #pragma unroll
            for (int mt = 0; mt < 4; mt++) {
                const int rlo = wm + mt * 16 + grp;
                const int rhi = rlo + 8;
                float4 w1 = *(const float4*)&red2[rlo * 4];
                float4 w2 = *(const float4*)&red2[rhi * 4];
                Srow[rlo] = Srow[rlo] * scllo[mt] + (w1.x + w1.y + w1.z + w1.w);
                Srow[rhi] = Srow[rhi] * sclhi[mt] + (w2.x + w2.y + w2.z + w2.w);
                Mrow[rlo] = newlo[mt];
                Mrow[rhi] = newhi[mt];
            }
        }

        // ---- O += P @ Ktile (B via ldsm.trans from key-major Ks) ----
        #pragma unroll
        for (int kk = 0; kk < 128; kk += 16) {
            uint32_t a[4][4], b[2][2];
            #pragma unroll
            for (int mt = 0; mt < 4; mt++)
                ldsm4(a[mt], pA + (uint32_t)((wm + mt * 16 + rl16) * APS_STR + kk + ko8) * 2);
            {
                uint32_t t4[4];
                ldsm4t(t4, kA + (uint32_t)((kk + la15) * AQ_STR + wn2 + lg8) * 2);
                b[0][0] = t4[0]; b[0][1] = t4[1];
                b[1][0] = t4[2]; b[1][1] = t4[3];
            }
            #pragma unroll
            for (int mt = 0; mt < 4; mt++)
                #pragma unroll
                for (int nt2 = 0; nt2 < 2; nt2++)
                    mma_f16(acc_o[mt][nt2], a[mt], b[nt2]);
        }
        __syncthreads();
    }

    // ---- epilogue: normalize, fp16-round, scatter to interleaved Ctx ----
    const int bq = z / NH;
    const int nh = z % NH;
    __half* Cbase = Ctx + ((size_t)(bq * LSEQ + l0)) * HID + nh;
    #pragma unroll
    for (int mt = 0; mt < 4; mt++) {
        const int rlo = wm + mt * 16 + grp;
        const int rhi = rlo + 8;
        const float ilo = 1.0f / Srow[rlo];
        const float ihi = 1.0f / Srow[rhi];
        #pragma unroll
        for (int nt2 = 0; nt2 < 2; nt2++) {
            const int d0 = wn2 + nt2 * 8 + 2 * tg;
            __half* plo = Cbase + (size_t)rlo * HID + d0 * NH;
            __half* phi = Cbase + (size_t)rhi * HID + d0 * NH;
            plo[0]  = __float2half_rn(acc_o[mt][nt2][0] * ilo);
            plo[NH] = __float2half_rn(acc_o[mt][nt2][1] * ilo);
            phi[0]  = __float2half_rn(acc_o[mt][nt2][2] * ihi);
            phi[NH] = __float2half_rn(acc_o[mt][nt2][3] * ihi);
        }
    }
}

// ---------------- host launch ----------------
extern "C" void kernel_launch(void* const* d_in, const int* in_sizes, int n_in,
                              void* d_out, int out_size)
{
    const float* x   = (const float*)d_in[0];
    const float* Wq  = (const float*)d_in[1];
    const float* Wk  = (const float*)d_in[2];
    // d_in[3] = Wv: unused (ctx contracts with K in the reference)
    const float* Wo  = (const float*)d_in[4];
    const float* W1  = (const float*)d_in[5];
    const float* b1  = (const float*)d_in[6];
    const float* W2  = (const float*)d_in[7];
    const float* b2  = (const float*)d_in[8];
    const float* g1  = (const float*)d_in[9];
    const float* be1 = (const float*)d_in[10];
    const float* g2  = (const float*)d_in[11];
    const float* be2 = (const float*)d_in[12];
    float* out = (float*)d_out;

    float  *QK, *x1f;
    __half *Qhh, *Khh, *xh, *Ctxh, *x1h, *Hfh, *Wqkh, *Worh, *W1h, *W2h;
    cudaGetSymbolAddress((void**)&QK,  g_QK);
    cudaGetSymbolAddress((void**)&x1f, g_x1f);
    cudaGetSymbolAddress((void**)&Qhh, g_Qhh);
    cudaGetSymbolAddress((void**)&Khh, g_Khh);
    cudaGetSymbolAddress((void**)&xh,  g_xh);
    cudaGetSymbolAddress((void**)&Ctxh,g_Ctxh);
    cudaGetSymbolAddress((void**)&x1h, g_x1h);
    cudaGetSymbolAddress((void**)&Hfh, g_Hfh);
    cudaGetSymbolAddress((void**)&Wqkh,g_Wqkh);
    cudaGetSymbolAddress((void**)&Worh,g_Worh);
    cudaGetSymbolAddress((void**)&W1h, g_W1h);
    cudaGetSymbolAddress((void**)&W2h, g_W2h);

    static bool attrs_set = false;
    if (!attrs_set) {
        cudaFuncSetAttribute(attn_fused, cudaFuncAttributeMaxDynamicSharedMemorySize, ATTN_SMEM_BYTES);
        cudaFuncSetAttribute(gemm_h<EPI_NONE, OUT_HEADS>,     cudaFuncAttributeMaxDynamicSharedMemorySize, GEMM_SMEM_BYTES);
        cudaFuncSetAttribute(gemm_h<EPI_BIAS_GELU, OUT_F16>,  cudaFuncAttributeMaxDynamicSharedMemorySize, GEMM_SMEM_BYTES);
        cudaFuncSetAttribute(gemm_h_splitk,                   cudaFuncAttributeMaxDynamicSharedMemorySize, GEMM_SMEM_BYTES);
        attrs_set = true;
    }

    const int n4 = MROWS * HID / 4;
    const dim3 tb(32, 8);

    // ---- operand conversion (merged) ----
    transpose_all_k<<<TALL, tb>>>(Wq, Wk, Wo, W1, W2);
    tohalf_k<<<(n4 + 255) / 256, 256>>>((const float4*)x, (__half2*)xh, n4);

    // ---- QK merged GEMM -> head-major Qh/Kh directly (Wq pre-scaled 1/8) ----
    gemm_h<EPI_NONE, OUT_HEADS><<<dim3(2 * HID / 128, MROWS / 128), 256, GEMM_SMEM_BYTES>>>(
        xh, Wqkh, Qhh, Khh, nullptr, MROWS, 2 * HID, HID);

    // ---- FP16 fused flash attention ----
    attn_fused<<<dim3(LSEQ / 128, NHEADS_TOT), 256, ATTN_SMEM_BYTES>>>(Qhh, Khh, Ctxh);

    // ---- Wo GEMM: fp16 split-K=2 -> fused reduce(+x) + LN -> x1f/x1h ----
    gemm_h_splitk<<<dim3(HID / 128, MROWS / 128, 2), 256, GEMM_SMEM_BYTES>>>(
        Ctxh, Worh, QK, MROWS, HID, HID, HID / 2);
    layernorm_fused_k<false, true><<<MROWS, 256>>>(QK, nullptr, x, g1, be1, x1f, x1h);

    // ---- MLP (fp16 mma) ----
    gemm_h<EPI_BIAS_GELU, OUT_F16><<<dim3(MLPD / 128, MROWS / 128), 256, GEMM_SMEM_BYTES>>>(
        x1h, W1h, Hfh, nullptr, b1, MROWS, MLPD, HID);
    gemm_h_splitk<<<dim3(HID / 128, MROWS / 128, 2), 256, GEMM_SMEM_BYTES>>>(
        Hfh, W2h, QK, MROWS, HID, MLPD, MLPD / 2);
    layernorm_fused_k<true, false><<<MROWS, 256>>>(QK, b2, x1f, g2, be2, out, nullptr);
}

// round 16
// speedup vs baseline: 1.2204x; 1.2204x over previous
#include <cuda_runtime.h>
#include <cuda_fp16.h>
#include <math.h>
#include <stdint.h>

#define BATCH 8
#define LSEQ  1024
#define HID   768
#define NH    12
#define DH    64
#define MLPD  3072
#define MROWS (BATCH*LSEQ)    // 8192
#define NHEADS_TOT (BATCH*NH) // 96

// ---------------- static scratch ----------------
__device__ float  g_QK [(size_t)MROWS*2*HID];  // split-K partials
__device__ float  g_x1f[MROWS*HID];
__device__ __half g_QKh[(size_t)MROWS*2*HID];
__device__ __half g_Qhh[MROWS*HID];
__device__ __half g_Khh[MROWS*HID];
__device__ __half g_xh  [MROWS*HID];
__device__ __half g_Ctxh[MROWS*HID];
__device__ __half g_x1h [MROWS*HID];
__device__ __half g_Hfh [(size_t)MROWS*MLPD];
__device__ __half g_Wqkh[(size_t)2*HID*HID];   // [1536][768] N-major (Wq pre-scaled 1/8)
__device__ __half g_Worh[HID*HID];
__device__ __half g_W1h [(size_t)MLPD*HID];
__device__ __half g_W2h [(size_t)HID*MLPD];

// ---------------- helpers ----------------
__device__ __forceinline__ float gelu_f(float v) {
    return 0.5f * v * (1.0f + erff(v * 0.7071067811865475f));
}

__device__ __forceinline__ void mma_f16(float* d, const uint32_t* a, const uint32_t* b) {
    asm volatile(
        "mma.sync.aligned.m16n8k16.row.col.f32.f16.f16.f32 "
        "{%0,%1,%2,%3}, {%4,%5,%6,%7}, {%8,%9}, {%0,%1,%2,%3};\n"
        : "+f"(d[0]), "+f"(d[1]), "+f"(d[2]), "+f"(d[3])
        : "r"(a[0]), "r"(a[1]), "r"(a[2]), "r"(a[3]),
          "r"(b[0]), "r"(b[1]));
}

__device__ __forceinline__ void ldsm4(uint32_t* r, uint32_t addr) {
    asm volatile("ldmatrix.sync.aligned.m8n8.x4.shared.b16 {%0,%1,%2,%3}, [%4];"
        : "=r"(r[0]), "=r"(r[1]), "=r"(r[2]), "=r"(r[3]) : "r"(addr));
}

__device__ __forceinline__ void ldsm4t(uint32_t* r, uint32_t addr) {
    asm volatile("ldmatrix.sync.aligned.m8n8.x4.trans.shared.b16 {%0,%1,%2,%3}, [%4];"
        : "=r"(r[0]), "=r"(r[1]), "=r"(r[2]), "=r"(r[3]) : "r"(addr));
}

__device__ __forceinline__ void cp16(uint32_t dst, const void* src) {
    asm volatile("cp.async.cg.shared.global [%0], [%1], 16;\n" :: "r"(dst), "l"(src));
}
__device__ __forceinline__ void cp_commit() {
    asm volatile("cp.async.commit_group;\n");
}
template<int N>
__device__ __forceinline__ void cp_wait() {
    asm volatile("cp.async.wait_group %0;\n" :: "n"(N));
}

enum { EPI_NONE = 0, EPI_BIAS_GELU = 2 };
enum { OUT_F32 = 0, OUT_F16 = 1 };

// ---------------- FP16 tensor-core GEMM: C = A(MxK) @ Bt(NxK)^T ----------------
#define HS_STR 40
#define STAGES 4
#define TILE_HALVES (128 * HS_STR)
#define TILE_BYTES  (TILE_HALVES * 2)
#define GEMM_SMEM_BYTES (STAGES * 2 * TILE_BYTES)

#define GEMM_CORE_LOOP(aBase, bBase) \
    _Pragma("unroll") \
    for (int kk = 0; kk < 32; kk += 16) { \
        uint32_t a[4][4], b[4][2]; \
        _Pragma("unroll") \
        for (int mt = 0; mt < 4; mt++) \
            ldsm4(a[mt], (aBase) + (uint32_t)((wm + mt * 16 + rl16) * HS_STR + kk + ko8) * 2); \
        _Pragma("unroll") \
        for (int nb = 0; nb < 2; nb++) { \
            uint32_t t4[4]; \
            ldsm4(t4, (bBase) + (uint32_t)((wn + nb * 16 + brow) * HS_STR + kk + bko) * 2); \
            b[2 * nb][0]     = t4[0]; \
            b[2 * nb][1]     = t4[1]; \
            b[2 * nb + 1][0] = t4[2]; \
            b[2 * nb + 1][1] = t4[3]; \
        } \
        _Pragma("unroll") \
        for (int mt = 0; mt < 4; mt++) \
            _Pragma("unroll") \
            for (int nt = 0; nt < 4; nt++) \
                mma_f16(acc[mt][nt], a[mt], b[nt]); \
    }

template<int EPI, int OUT>
__global__ __launch_bounds__(256, 2) void gemm_h(
    const __half* __restrict__ A, const __half* __restrict__ Bt, void* __restrict__ Cv,
    const float* __restrict__ bias, int M, int N, int K)
{
    extern __shared__ __half hsm[];
    const uint32_t sA = (uint32_t)__cvta_generic_to_shared(hsm);
    const uint32_t sB = sA + STAGES * TILE_BYTES;

    const int tid  = threadIdx.x;
    const int lane = tid & 31;
    const int warp = tid >> 5;
    const int grp  = lane >> 2;
    const int tg   = lane & 3;
    const int wm   = (warp >> 2) * 64;
    const int wn   = (warp & 3) * 32;
    const int bx   = blockIdx.x;
    const int by   = blockIdx.y;

    const int rl16 = lane & 15;
    const int ko8  = (lane >> 4) << 3;
    const int brow = (lane & 7) + ((lane >> 4) << 3);
    const int bko  = ((lane >> 3) & 1) << 3;

    const __half* Abase = A  + (size_t)(by * 128) * K;
    const __half* Bbase = Bt + (size_t)(bx * 128) * K;

    float acc[4][4][4];
    #pragma unroll
    for (int i = 0; i < 4; i++)
        #pragma unroll
        for (int j = 0; j < 4; j++)
            #pragma unroll
            for (int r = 0; r < 4; r++) acc[i][j][r] = 0.0f;

    const int nt_ = K >> 5;

    auto issue = [&](int t) {
        const int st = t & (STAGES - 1);
        const int k0 = t << 5;
        const uint32_t aoff = sA + st * TILE_BYTES;
        const uint32_t boff = sB + st * TILE_BYTES;
        #pragma unroll
        for (int i = 0; i < 2; i++) {
            const int c = tid + 256 * i;
            const int r = c >> 2, ch = (c & 3) * 8;
            cp16(aoff + (uint32_t)(r * HS_STR + ch) * 2, Abase + (size_t)r * K + k0 + ch);
            cp16(boff + (uint32_t)(r * HS_STR + ch) * 2, Bbase + (size_t)r * K + k0 + ch);
        }
        cp_commit();
    };

    #pragma unroll
    for (int t = 0; t < STAGES - 1; t++) issue(t);

    for (int t = 0; t < nt_; t++) {
        cp_wait<STAGES - 2>();
        __syncthreads();
        const int cur = t & (STAGES - 1);
        const uint32_t aBase = sA + cur * TILE_BYTES;
        const uint32_t bBase = sB + cur * TILE_BYTES;
        GEMM_CORE_LOOP(aBase, bBase)
        if (t + STAGES - 1 < nt_) issue(t + STAGES - 1);
        else cp_commit();
    }

    #pragma unroll
    for (int mt = 0; mt < 4; mt++) {
        #pragma unroll
        for (int nt = 0; nt < 4; nt++) {
            const int r0 = by * 128 + wm + mt * 16 + grp;
            const int c0 = bx * 128 + wn + nt * 8 + tg * 2;
            float v0 = acc[mt][nt][0], v1 = acc[mt][nt][1];
            float v2 = acc[mt][nt][2], v3 = acc[mt][nt][3];
            if (EPI == EPI_BIAS_GELU) {
                const float2 bv = *(const float2*)&bias[c0];
                v0 = gelu_f(v0 + bv.x); v1 = gelu_f(v1 + bv.y);
                v2 = gelu_f(v2 + bv.x); v3 = gelu_f(v3 + bv.y);
            }
            if (OUT == OUT_F16) {
                __half* Ch = (__half*)Cv;
                *(__half2*)&Ch[(size_t)r0 * N + c0] = __floats2half2_rn(v0, v1);
                *(__half2*)&Ch[(size_t)(r0 + 8) * N + c0] = __floats2half2_rn(v2, v3);
            } else {
                float* Cf = (float*)Cv;
                float2 w0 = {v0, v1}, w1 = {v2, v3};
                *(float2*)&Cf[(size_t)r0 * N + c0] = w0;
                *(float2*)&Cf[(size_t)(r0 + 8) * N + c0] = w1;
            }
        }
    }
}

// ---------------- FP16 split-K=2 partial GEMM ----------------
__global__ __launch_bounds__(256, 2) void gemm_h_splitk(
    const __half* __restrict__ A, const __half* __restrict__ Bt, float* __restrict__ Cp,
    int M, int N, int ldk, int Khalf)
{
    extern __shared__ __half hsm[];
    const uint32_t sA = (uint32_t)__cvta_generic_to_shared(hsm);
    const uint32_t sB = sA + STAGES * TILE_BYTES;

    const int tid  = threadIdx.x;
    const int lane = tid & 31;
    const int warp = tid >> 5;
    const int grp  = lane >> 2;
    const int tg   = lane & 3;
    const int wm   = (warp >> 2) * 64;
    const int wn   = (warp & 3) * 32;
    const int bx   = blockIdx.x;
    const int by   = blockIdx.y;
    const int z    = blockIdx.z;

    const int rl16 = lane & 15;
    const int ko8  = (lane >> 4) << 3;
    const int brow = (lane & 7) + ((lane >> 4) << 3);
    const int bko  = ((lane >> 3) & 1) << 3;

    const __half* Abase = A  + (size_t)(by * 128) * ldk + (size_t)z * Khalf;
    const __half* Bbase = Bt + (size_t)(bx * 128) * ldk + (size_t)z * Khalf;

    float acc[4][4][4];
    #pragma unroll
    for (int i = 0; i < 4; i++)
        #pragma unroll
        for (int j = 0; j < 4; j++)
            #pragma unroll
            for (int r = 0; r < 4; r++) acc[i][j][r] = 0.0f;

    const int nt_ = Khalf >> 5;

    auto issue = [&](int t) {
        const int st = t & (STAGES - 1);
        const int k0 = t << 5;
        const uint32_t aoff = sA + st * TILE_BYTES;
        const uint32_t boff = sB + st * TILE_BYTES;
        #pragma unroll
        for (int i = 0; i < 2; i++) {
            const int c = tid + 256 * i;
            const int r = c >> 2, ch = (c & 3) * 8;
            cp16(aoff + (uint32_t)(r * HS_STR + ch) * 2, Abase + (size_t)r * ldk + k0 + ch);
            cp16(boff + (uint32_t)(r * HS_STR + ch) * 2, Bbase + (size_t)r * ldk + k0 + ch);
        }
        cp_commit();
    };

    #pragma unroll
    for (int t = 0; t < STAGES - 1; t++) issue(t);

    for (int t = 0; t < nt_; t++) {
        cp_wait<STAGES - 2>();
        __syncthreads();
        const int cur = t & (STAGES - 1);
        const uint32_t aBase = sA + cur * TILE_BYTES;
        const uint32_t bBase = sB + cur * TILE_BYTES;
        GEMM_CORE_LOOP(aBase, bBase)
        if (t + STAGES - 1 < nt_) issue(t + STAGES - 1);
        else cp_commit();
    }

    float* Cz = Cp + (size_t)z * M * N;
    #pragma unroll
    for (int mt = 0; mt < 4; mt++) {
        #pragma unroll
        for (int nt = 0; nt < 4; nt++) {
            const int r0 = by * 128 + wm + mt * 16 + grp;
            const int c0 = bx * 128 + wn + nt * 8 + tg * 2;
            float2 w0 = {acc[mt][nt][0], acc[mt][nt][1]};
            float2 w1 = {acc[mt][nt][2], acc[mt][nt][3]};
            *(float2*)&Cz[(size_t)r0 * N + c0] = w0;
            *(float2*)&Cz[(size_t)(r0 + 8) * N + c0] = w1;
        }
    }
}

// ---------------- fused split-K reduce + layernorm ----------------
template<bool BIAS, bool HOUT>
__global__ __launch_bounds__(256) void layernorm_fused_k(
    const float* __restrict__ p, const float* __restrict__ bias,
    const float* __restrict__ res, const float* __restrict__ g,
    const float* __restrict__ be, float* __restrict__ Yf, __half* __restrict__ Yh)
{
    const int row = blockIdx.x;
    const float* p0 = p + (size_t)row * HID;
    const float* p1 = p + (size_t)MROWS * HID + (size_t)row * HID;
    const float* r  = res + (size_t)row * HID;
    const int tid = threadIdx.x;
    __shared__ float vbuf[HID];
    __shared__ float shs[8], shss[8];

    float s = 0.0f, ss = 0.0f;
    for (int c = tid; c < HID; c += 256) {
        float v = p0[c] + p1[c] + r[c];
        if (BIAS) v += bias[c];
        vbuf[c] = v;
        s += v;
        ss = fmaf(v, v, ss);
    }
    #pragma unroll
    for (int o = 16; o; o >>= 1) {
        s  += __shfl_xor_sync(0xffffffffu, s, o);
        ss += __shfl_xor_sync(0xffffffffu, ss, o);
    }
    if ((tid & 31) == 0) { shs[tid >> 5] = s; shss[tid >> 5] = ss; }
    __syncthreads();
    if (tid == 0) {
        float a = 0.0f, b = 0.0f;
        #pragma unroll
        for (int i = 0; i < 8; i++) { a += shs[i]; b += shss[i]; }
        shs[0] = a; shss[0] = b;
    }
    __syncthreads();
    const float mu  = shs[0]  * (1.0f / HID);
    const float var = shss[0] * (1.0f / HID) - mu * mu;
    const float inv = rsqrtf(var + 1e-5f);
    for (int c = tid; c < HID; c += 256) {
        float v = (vbuf[c] - mu) * inv * g[c] + be[c];
        Yf[(size_t)row * HID + c] = v;
        if (HOUT) Yh[(size_t)row * HID + c] = __float2half_rn(v);
    }
}

// ---------------- merged weight transpose+fp16 (one launch) ----------------
#define TQ  576
#define T1  2304
#define TALL (3*TQ + 2*T1)

__global__ void transpose_all_k(const float* __restrict__ Wq, const float* __restrict__ Wk,
                                const float* __restrict__ Wo, const float* __restrict__ W1,
                                const float* __restrict__ W2) {
    __shared__ float tb[32][33];
    int bid = blockIdx.x;
    const float* W; __half* Wt; int K, N, nx; float scale = 1.0f;
    if (bid < TQ)            { W = Wq; Wt = g_Wqkh;                       K = HID;  N = HID;  nx = 24; scale = 0.125f; }
    else if (bid < 2 * TQ)   { bid -= TQ;     W = Wk; Wt = g_Wqkh + (size_t)HID * HID; K = HID;  N = HID;  nx = 24; }
    else if (bid < 3 * TQ)   { bid -= 2 * TQ; W = Wo; Wt = g_Worh;        K = HID;  N = HID;  nx = 24; }
    else if (bid < 3 * TQ + T1) { bid -= 3 * TQ; W = W1; Wt = g_W1h;      K = HID;  N = MLPD; nx = 96; }
    else                     { bid -= 3 * TQ + T1; W = W2; Wt = g_W2h;    K = MLPD; N = HID;  nx = 24; }
    const int n0 = (bid % nx) * 32;
    const int k0 = (bid / nx) * 32;
    const int tx = threadIdx.x, ty = threadIdx.y;
    #pragma unroll
    for (int j = ty; j < 32; j += 8)
        tb[j][tx] = W[(size_t)(k0 + j) * N + n0 + tx];
    __syncthreads();
    #pragma unroll
    for (int j = ty; j < 32; j += 8)
        Wt[(size_t)(n0 + j) * K + k0 + tx] = __float2half_rn(tb[tx][j] * scale);
}

__global__ void tohalf_k(const float4* __restrict__ in, __half2* __restrict__ out, int n4) {
    int i = blockIdx.x * blockDim.x + threadIdx.x;
    if (i >= n4) return;
    float4 v = in[i];
    out[2 * i]     = __floats2half2_rn(v.x, v.y);
    out[2 * i + 1] = __floats2half2_rn(v.z, v.w);
}

// ---------------- permute to head-major (half -> half; Wq already scaled) ----------------
__global__ void to_head2_k(const __half* __restrict__ QK,
                           __half* __restrict__ Qh, __half* __restrict__ Kh) {
    int idx = blockIdx.x * blockDim.x + threadIdx.x;
    if (idx >= MROWS * HID) return;
    int d = idx & 63;
    int l = (idx >> 6) & 1023;
    int z = idx >> 16;
    int n = z % NH, b = z / NH;
    const size_t src = (size_t)(b * LSEQ + l) * (2 * HID) + d * NH + n;
    Qh[idx] = QK[src];
    Kh[idx] = QK[src + HID];
}

// ---------------- FP16 fused flash attention ----------------
// Double-buffered cp.async K prefetch; O-mma B via ldsm.trans from key-major Ks.
#define AQ_STR  72
#define APS_STR 136
#define KBUF_HALVES (128 * AQ_STR)
#define ATTN_HALVES (128*AQ_STR + 2*KBUF_HALVES + 128*APS_STR)
#define ATTN_FLOATS (128 + 128 + 512 + 512)
#define ATTN_SMEM_BYTES (ATTN_HALVES * 2 + ATTN_FLOATS * 4)

__global__ __launch_bounds__(256) void attn_fused(
    const __half* __restrict__ Qh, const __half* __restrict__ Kh, __half* __restrict__ Ctx)
{
    extern __shared__ __half asm_[];
    __half* Qs = asm_;                         // [128][AQ_STR]
    __half* Ks = Qs + 128 * AQ_STR;            // [2][128][AQ_STR]
    __half* Ps = Ks + 2 * KBUF_HALVES;         // [128][APS_STR]
    float* Mrow = (float*)(Ps + 128 * APS_STR);
    float* Srow = Mrow + 128;
    float* red1 = Srow + 128;
    float* red2 = red1 + 512;

    const uint32_t qA  = (uint32_t)__cvta_generic_to_shared(Qs);
    const uint32_t kA0 = (uint32_t)__cvta_generic_to_shared(Ks);
    const uint32_t pA  = (uint32_t)__cvta_generic_to_shared(Ps);

    const int z   = blockIdx.y;
    const int l0  = blockIdx.x * 128;
    const int tid = threadIdx.x;
    const int lane = tid & 31;
    const int warp = tid >> 5;
    const int grp  = lane >> 2;
    const int tg   = lane & 3;
    const int wm   = (warp >> 2) * 64;
    const int wn   = (warp & 3) * 32;
    const int wn2  = (warp & 3) * 16;
    const int wc   = warp & 3;

    const int rl16 = lane & 15;
    const int ko8  = (lane >> 4) << 3;
    const int brow = (lane & 7) + ((lane >> 4) << 3);
    const int bko  = ((lane >> 3) & 1) << 3;
    const int la15 = lane & 15;
    const int lg8  = (lane >> 4) << 3;

    const __half* Qbase = Qh + ((size_t)z * LSEQ + l0) * DH;
    const __half* Kbase = Kh + (size_t)z * LSEQ * DH;

    if (tid < 128) { Mrow[tid] = -3.0e38f; Srow[tid] = 0.0f; }

    // prefetch K tile 0 via cp.async (overlaps Q staging below)
    auto issueK = [&](int m, int buf) {
        const __half* Kt = Kbase + (size_t)m * 128 * DH;
        const uint32_t base = kA0 + (uint32_t)(buf * KBUF_HALVES) * 2;
        #pragma unroll
        for (int i = 0; i < 4; i++) {
            const int f = tid + 256 * i;
            const int r = f >> 3, c8 = (f & 7) * 8;
            cp16(base + (uint32_t)(r * AQ_STR + c8) * 2, Kt + (size_t)r * DH + c8);
        }
        cp_commit();
    };
    issueK(0, 0);

    #pragma unroll
    for (int i = 0; i < 8; i++) {
        const int f = tid + 256 * i;
        const int r = f >> 4, c4 = (f & 15) * 4;
        uint2 v = *(const uint2*)(Qbase + r * DH + c4);
        *(uint2*)&Qs[r * AQ_STR + c4] = v;
    }

    float acc_o[4][2][4];
    #pragma unroll
    for (int i = 0; i < 4; i++)
        #pragma unroll
        for (int j = 0; j < 2; j++)
            #pragma unroll
            for (int r = 0; r < 4; r++) acc_o[i][j][r] = 0.0f;

    for (int mtile = 0; mtile < LSEQ / 128; mtile++) {
        cp_wait<0>();
        __syncthreads();
        if (mtile + 1 < LSEQ / 128) issueK(mtile + 1, (mtile + 1) & 1);

        const uint32_t kA = kA0 + (uint32_t)((mtile & 1) * KBUF_HALVES) * 2;

        // ---- S = Q @ K^T (fp16 mma, K=64) ----
        float s[4][4][4];
        #pragma unroll
        for (int i = 0; i < 4; i++)
            #pragma unroll
            for (int j = 0; j < 4; j++)
                #pragma unroll
                for (int r = 0; r < 4; r++) s[i][j][r] = 0.0f;

        #pragma unroll
        for (int kk = 0; kk < DH; kk += 16) {
            uint32_t a[4][4], b[4][2];
            #pragma unroll
            for (int mt = 0; mt < 4; mt++)
                ldsm4(a[mt], qA + (uint32_t)((wm + mt * 16 + rl16) * AQ_STR + kk + ko8) * 2);
            #pragma unroll
            for (int nb = 0; nb < 2; nb++) {
                uint32_t t4[4];
                ldsm4(t4, kA + (uint32_t)((wn + nb * 16 + brow) * AQ_STR + kk + bko) * 2);
                b[2 * nb][0]     = t4[0];
                b[2 * nb][1]     = t4[1];
                b[2 * nb + 1][0] = t4[2];
                b[2 * nb + 1][1] = t4[3];
            }
            #pragma unroll
            for (int mt = 0; mt < 4; mt++)
                #pragma unroll
                for (int nt = 0; nt < 4; nt++)
                    mma_f16(s[mt][nt], a[mt], b[nt]);
        }

        // ---- Phase A: per-warp row max ----
        #pragma unroll
        for (int mt = 0; mt < 4; mt++) {
            float mlo = -3.0e38f, mhi = -3.0e38f;
            #pragma unroll
            for (int nt = 0; nt < 4; nt++) {
                mlo = fmaxf(mlo, fmaxf(s[mt][nt][0], s[mt][nt][1]));
                mhi = fmaxf(mhi, fmaxf(s[mt][nt][2], s[mt][nt][3]));
            }
            mlo = fmaxf(mlo, __shfl_xor_sync(0xffffffffu, mlo, 1));
            mlo = fmaxf(mlo, __shfl_xor_sync(0xffffffffu, mlo, 2));
            mhi = fmaxf(mhi, __shfl_xor_sync(0xffffffffu, mhi, 1));
            mhi = fmaxf(mhi, __shfl_xor_sync(0xffffffffu, mhi, 2));
            if (tg == 0) {
                red1[(wm + mt * 16 + grp) * 4 + wc]     = mlo;
                red1[(wm + mt * 16 + grp + 8) * 4 + wc] = mhi;
            }
        }
        __syncthreads();

        // ---- Phase B ----
        float newlo[4], newhi[4], scllo[4], sclhi[4];
        #pragma unroll
        for (int mt = 0; mt < 4; mt++) {
            const int rlo = wm + mt * 16 + grp;
            const int rhi = rlo + 8;
            float4 v1 = *(const float4*)&red1[rlo * 4];
            float4 v2 = *(const float4*)&red1[rhi * 4];
            float tlo = fmaxf(fmaxf(v1.x, v1.y), fmaxf(v1.z, v1.w));
            float thi = fmaxf(fmaxf(v2.x, v2.y), fmaxf(v2.z, v2.w));
            float oldlo = Mrow[rlo], oldhi = Mrow[rhi];
            float nlo = fmaxf(oldlo, tlo), nhi = fmaxf(oldhi, thi);
            newlo[mt] = nlo; newhi[mt] = nhi;
            scllo[mt] = __expf(oldlo - nlo);
            sclhi[mt] = __expf(oldhi - nhi);

            float pslo = 0.0f, pshi = 0.0f;
            #pragma unroll
            for (int nt = 0; nt < 4; nt++) {
                const int c = wn + nt * 8 + 2 * tg;
                float p0 = __expf(s[mt][nt][0] - nlo);
                float p1 = __expf(s[mt][nt][1] - nlo);
                float p2 = __expf(s[mt][nt][2] - nhi);
                float p3 = __expf(s[mt][nt][3] - nhi);
                *(__half2*)&Ps[rlo * APS_STR + c] = __floats2half2_rn(p0, p1);
                *(__half2*)&Ps[rhi * APS_STR + c] = __floats2half2_rn(p2, p3);
                pslo += p0 + p1;
                pshi += p2 + p3;
            }
            pslo += __shfl_xor_sync(0xffffffffu, pslo, 1);
            pslo += __shfl_xor_sync(0xffffffffu, pslo, 2);
            pshi += __shfl_xor_sync(0xffffffffu, pshi, 1);
            pshi += __shfl_xor_sync(0xffffffffu, pshi, 2);
            if (tg == 0) {
                red2[rlo * 4 + wc] = pslo;
                red2[rhi * 4 + wc] = pshi;
            }
            #pragma unroll
            for (int nt2 = 0; nt2 < 2; nt2++) {
                acc_o[mt][nt2][0] *= scllo[mt];
                acc_o[mt][nt2][1] *= scllo[mt];
                acc_o[mt][nt2][2] *= sclhi[mt];
                acc_o[mt][nt2][3] *= sclhi[mt];
            }
        }
        __syncthreads();

        // ---- Phase C ----
        if (wc == 0 && tg == 0) {
            #pragma unroll
            for (int mt = 0; mt < 4; mt++) {
                const int rlo = wm + mt * 16 + grp;
                const int rhi = rlo + 8;
                float4 w1 = *(const float4*)&red2[rlo * 4];
                float4 w2 = *(const float4*)&red2[rhi * 4];
                Srow[rlo] = Srow[rlo] * scllo[mt] + (w1.x + w1.y + w1.z + w1.w);
                Srow[rhi] = Srow[rhi] * sclhi[mt] + (w2.x + w2.y + w2.z + w2.w);
                Mrow[rlo] = newlo[mt];
                Mrow[rhi] = newhi[mt];
            }
        }

        // ---- O += P @ Ktile (B via ldsm.trans) ----
        #pragma unroll
        for (int kk = 0; kk < 128; kk += 16) {
            uint32_t a[4][4], b[2][2];
            #pragma unroll
            for (int mt = 0; mt < 4; mt++)
                ldsm4(a[mt], pA + (uint32_t)((wm + mt * 16 + rl16) * APS_STR + kk + ko8) * 2);
            {
                uint32_t t4[4];
                ldsm4t(t4, kA + (uint32_t)((kk + la15) * AQ_STR + wn2 + lg8) * 2);
                b[0][0] = t4[0]; b[0][1] = t4[1];
                b[1][0] = t4[2]; b[1][1] = t4[3];
            }
            #pragma unroll
            for (int mt = 0; mt < 4; mt++)
                #pragma unroll
                for (int nt2 = 0; nt2 < 2; nt2++)
                    mma_f16(acc_o[mt][nt2], a[mt], b[nt2]);
        }
        __syncthreads();
    }

    // ---- epilogue: normalize, fp16-round, scatter to interleaved Ctx ----
    const int bq = z / NH;
    const int nh = z % NH;
    __half* Cbase = Ctx + ((size_t)(bq * LSEQ + l0)) * HID + nh;
    #pragma unroll
    for (int mt = 0; mt < 4; mt++) {
        const int rlo = wm + mt * 16 + grp;
        const int rhi = rlo + 8;
        const float ilo = 1.0f / Srow[rlo];
        const float ihi = 1.0f / Srow[rhi];
        #pragma unroll
        for (int nt2 = 0; nt2 < 2; nt2++) {
            const int d0 = wn2 + nt2 * 8 + 2 * tg;
            __half* plo = Cbase + (size_t)rlo * HID + d0 * NH;
            __half* phi = Cbase + (size_t)rhi * HID + d0 * NH;
            plo[0]  = __float2half_rn(acc_o[mt][nt2][0] * ilo);
            plo[NH] = __float2half_rn(acc_o[mt][nt2][1] * ilo);
            phi[0]  = __float2half_rn(acc_o[mt][nt2][2] * ihi);
            phi[NH] = __float2half_rn(acc_o[mt][nt2][3] * ihi);
        }
    }
}

// ---------------- host launch ----------------
extern "C" void kernel_launch(void* const* d_in, const int* in_sizes, int n_in,
                              void* d_out, int out_size)
{
    const float* x   = (const float*)d_in[0];
    const float* Wq  = (const float*)d_in[1];
    const float* Wk  = (const float*)d_in[2];
    // d_in[3] = Wv: unused (ctx contracts with K in the reference)
    const float* Wo  = (const float*)d_in[4];
    const float* W1  = (const float*)d_in[5];
    const float* b1  = (const float*)d_in[6];
    const float* W2  = (const float*)d_in[7];
    const float* b2  = (const float*)d_in[8];
    const float* g1  = (const float*)d_in[9];
    const float* be1 = (const float*)d_in[10];
    const float* g2  = (const float*)d_in[11];
    const float* be2 = (const float*)d_in[12];
    float* out = (float*)d_out;

    float  *QK, *x1f;
    __half *QKh, *Qhh, *Khh, *xh, *Ctxh, *x1h, *Hfh, *Wqkh, *Worh, *W1h, *W2h;
    cudaGetSymbolAddress((void**)&QK,  g_QK);
    cudaGetSymbolAddress((void**)&x1f, g_x1f);
    cudaGetSymbolAddress((void**)&QKh, g_QKh);
    cudaGetSymbolAddress((void**)&Qhh, g_Qhh);
    cudaGetSymbolAddress((void**)&Khh, g_Khh);
    cudaGetSymbolAddress((void**)&xh,  g_xh);
    cudaGetSymbolAddress((void**)&Ctxh,g_Ctxh);
    cudaGetSymbolAddress((void**)&x1h, g_x1h);
    cudaGetSymbolAddress((void**)&Hfh, g_Hfh);
    cudaGetSymbolAddress((void**)&Wqkh,g_Wqkh);
    cudaGetSymbolAddress((void**)&Worh,g_Worh);
    cudaGetSymbolAddress((void**)&W1h, g_W1h);
    cudaGetSymbolAddress((void**)&W2h, g_W2h);

    static bool attrs_set = false;
    if (!attrs_set) {
        cudaFuncSetAttribute(attn_fused, cudaFuncAttributeMaxDynamicSharedMemorySize, ATTN_SMEM_BYTES);
        cudaFuncSetAttribute(gemm_h<EPI_NONE, OUT_F16>,      cudaFuncAttributeMaxDynamicSharedMemorySize, GEMM_SMEM_BYTES);
        cudaFuncSetAttribute(gemm_h<EPI_BIAS_GELU, OUT_F16>, cudaFuncAttributeMaxDynamicSharedMemorySize, GEMM_SMEM_BYTES);
        cudaFuncSetAttribute(gemm_h_splitk,                  cudaFuncAttributeMaxDynamicSharedMemorySize, GEMM_SMEM_BYTES);
        attrs_set = true;
    }

    const int nperm = MROWS * HID;
    const int n4 = MROWS * HID / 4;
    const dim3 tb(32, 8);

    // ---- operand conversion (merged) ----
    transpose_all_k<<<TALL, tb>>>(Wq, Wk, Wo, W1, W2);
    tohalf_k<<<(n4 + 255) / 256, 256>>>((const float4*)x, (__half2*)xh, n4);

    // ---- QK merged GEMM (fp16 -> fp16 output, coalesced) ----
    gemm_h<EPI_NONE, OUT_F16><<<dim3(2 * HID / 128, MROWS / 128), 256, GEMM_SMEM_BYTES>>>(
        xh, Wqkh, QKh, nullptr, MROWS, 2 * HID, HID);

    to_head2_k<<<(nperm + 255) / 256, 256>>>(QKh, Qhh, Khh);

    // ---- FP16 fused flash attention (K prefetch double-buffered) ----
    attn_fused<<<dim3(LSEQ / 128, NHEADS_TOT), 256, ATTN_SMEM_BYTES>>>(Qhh, Khh, Ctxh);

    // ---- Wo GEMM: fp16 split-K=2 -> fused reduce(+x) + LN -> x1f/x1h ----
    gemm_h_splitk<<<dim3(HID / 128, MROWS / 128, 2), 256, GEMM_SMEM_BYTES>>>(
        Ctxh, Worh, QK, MROWS, HID, HID, HID / 2);
    layernorm_fused_k<false, true><<<MROWS, 256>>>(QK, nullptr, x, g1, be1, x1f, x1h);

    // ---- MLP (fp16 mma) ----
    gemm_h<EPI_BIAS_GELU, OUT_F16><<<dim3(MLPD / 128, MROWS / 128), 256, GEMM_SMEM_BYTES>>>(
        x1h, W1h, Hfh, b1, MROWS, MLPD, HID);
    gemm_h_splitk<<<dim3(HID / 128, MROWS / 128, 2), 256, GEMM_SMEM_BYTES>>>(
        Hfh, W2h, QK, MROWS, HID, MLPD, MLPD / 2);
    layernorm_fused_k<true, false><<<MROWS, 256>>>(QK, b2, x1f, g2, be2, out, nullptr);
}